// round 3
// baseline (speedup 1.0000x reference)
#include <cuda_runtime.h>

// y[t, f] = x[t, f] * w[f] + b[f]
// x: [8192, 4096] f32, w/b: [4096] f32, out: [8192, 4096] f32
// HBM stream kernel. Each thread: 4 rows x 1 float4 column.
// - MLP=4 independent x loads per thread
// - one w/b load pair amortized over 4 FMNA groups
// - streaming cache hints on x/out (read-once / write-once)

static constexpr int TOKENS = 8192;
static constexpr int FEATURES = 4096;
static constexpr int F4_PER_ROW = FEATURES / 4;              // 1024
static constexpr int ROWS_PER_THREAD = 4;
static constexpr int TOTAL_GROUPS = (TOKENS / ROWS_PER_THREAD) * F4_PER_ROW;  // 2,097,152

__global__ void __launch_bounds__(256) one_to_one_kernel(
    const float4* __restrict__ x,
    const float4* __restrict__ w,
    const float4* __restrict__ b,
    float4* __restrict__ out)
{
    int i = blockIdx.x * blockDim.x + threadIdx.x;
    if (i >= TOTAL_GROUPS) return;

    int c  = i & (F4_PER_ROW - 1);     // column (float4 units)
    int rg = i >> 10;                  // row group
    int base = rg * (ROWS_PER_THREAD * F4_PER_ROW) + c;

    // Front-batched independent loads: MLP = 4
    float4 x0 = __ldcs(&x[base]);
    float4 x1 = __ldcs(&x[base + 1 * F4_PER_ROW]);
    float4 x2 = __ldcs(&x[base + 2 * F4_PER_ROW]);
    float4 x3 = __ldcs(&x[base + 3 * F4_PER_ROW]);

    float4 wv = __ldg(&w[c]);
    float4 bv = __ldg(&b[c]);

    float4 r0, r1, r2, r3;
    r0.x = fmaf(x0.x, wv.x, bv.x); r0.y = fmaf(x0.y, wv.y, bv.y);
    r0.z = fmaf(x0.z, wv.z, bv.z); r0.w = fmaf(x0.w, wv.w, bv.w);
    r1.x = fmaf(x1.x, wv.x, bv.x); r1.y = fmaf(x1.y, wv.y, bv.y);
    r1.z = fmaf(x1.z, wv.z, bv.z); r1.w = fmaf(x1.w, wv.w, bv.w);
    r2.x = fmaf(x2.x, wv.x, bv.x); r2.y = fmaf(x2.y, wv.y, bv.y);
    r2.z = fmaf(x2.z, wv.z, bv.z); r2.w = fmaf(x2.w, wv.w, bv.w);
    r3.x = fmaf(x3.x, wv.x, bv.x); r3.y = fmaf(x3.y, wv.y, bv.y);
    r3.z = fmaf(x3.z, wv.z, bv.z); r3.w = fmaf(x3.w, wv.w, bv.w);

    __stcs(&out[base],                  r0);
    __stcs(&out[base + 1 * F4_PER_ROW], r1);
    __stcs(&out[base + 2 * F4_PER_ROW], r2);
    __stcs(&out[base + 3 * F4_PER_ROW], r3);
}

extern "C" void kernel_launch(void* const* d_in, const int* in_sizes, int n_in,
                              void* d_out, int out_size)
{
    const float4* x = (const float4*)d_in[0];
    const float4* w = (const float4*)d_in[1];
    const float4* b = (const float4*)d_in[2];
    float4* out = (float4*)d_out;

    const int threads = 256;
    const int blocks = (TOTAL_GROUPS + threads - 1) / threads;  // 8192
    one_to_one_kernel<<<blocks, threads>>>(x, w, b, out);
}